// round 11
// baseline (speedup 1.0000x reference)
#include <cuda_runtime.h>
#include <cstdint>

#define WID 256
#define HGT 256
#define HW  65536
#define BATCH 8
#define BHW 524288

// ---------------- scratch ----------------
__device__ float g_vs[BHW];                        // V/sf
__device__ float g_actA[(size_t)BATCH * HW * 32];  // NHWC 32ch (conv1 out, conv3 out)
__device__ float g_actB[(size_t)BATCH * HW * 64];  // NHWC 64ch (conv2 out)
__device__ float g_w2p[9 * 4 * 2 * 32 * 12];       // conv2 weights lane-packed (nhalf split)
__device__ float g_w3p[9 * 8 * 32 * 12];           // conv3 weights lane-packed (full-n)

// ---------------- helpers ----------------
__device__ __forceinline__ float rna_tf32(float x) {
    uint32_t u;
    asm("cvt.rna.tf32.f32 %0, %1;" : "=r"(u) : "f"(x));
    return __uint_as_float(u);
}
__device__ __forceinline__ uint32_t fau(float x) { return __float_as_uint(x); }

#define MMA_TF32(d, a, b0, b1) \
    asm volatile("mma.sync.aligned.m16n8k8.row.col.f32.tf32.tf32.f32 " \
        "{%0,%1,%2,%3}, {%4,%5,%6,%7}, {%8,%9}, {%0,%1,%2,%3};" \
        : "+f"((d)[0]), "+f"((d)[1]), "+f"((d)[2]), "+f"((d)[3]) \
        : "r"((a)[0]), "r"((a)[1]), "r"((a)[2]), "r"((a)[3]), "r"(b0), "r"(b1))

// ---------------- prep ----------------
__global__ void __launch_bounds__(256) prep_kernel(
    const float* __restrict__ inp, const float* __restrict__ H0,
    const float* __restrict__ C0, const float* __restrict__ c2,
    const float* __restrict__ sf, float* __restrict__ out,
    float* __restrict__ vs)
{
    int idx = blockIdx.x * 256 + threadIdx.x;
    if (idx >= BHW) return;
    int b = idx >> 16, rem = idx & 65535, y = rem >> 8, x = rem & 255;

    float c  = inp[idx];
    float up = (y > 0)       ? inp[idx - WID] : 0.f;
    float dn = (y < HGT - 1) ? inp[idx + WID] : 0.f;
    float lf = (x > 0)       ? inp[idx - 1]   : 0.f;
    float rt = (x < WID - 1) ? inp[idx + 1]   : 0.f;
    float lap = up + dn + lf + rt - 4.f * c;

    float c0v = C0[(size_t)b * 2 * HW + rem];
    float Hv  = 2.f * c - c0v + c2[0] * lap;
    float V   = c - H0[idx];

    out[(size_t)BHW + idx]     = Hv;
    out[4 * (size_t)BHW + idx] = V;
    out[2 * (size_t)BHW + (size_t)b * 2 * HW + rem]      = c;
    out[2 * (size_t)BHW + (size_t)b * 2 * HW + HW + rem] = c0v;
    vs[idx] = V / sf[0];
}

// ---------------- weight pack ----------------
// conv2: R10 nh-split layout. conv3: R8 full-n layout (stride 12, fb[8]).
__global__ void __launch_bounds__(256) w_pack_k(
    const float* __restrict__ w2, const float* __restrict__ w3,
    float* __restrict__ p2, float* __restrict__ p3)
{
    int idx = blockIdx.x * 256 + threadIdx.x;   // < 18432
    {   // conv2: e in 0..7 -> nt_local = e>>1, ksel = e&1
        int e = idx & 7, lane = (idx >> 3) & 31;
        int nh = (idx >> 8) & 1, kk = (idx >> 9) & 3, tap = idx >> 11;
        int qid = lane >> 2, tig = lane & 3;
        int n = (nh * 4 + (e >> 1)) * 8 + qid;
        int k = kk * 8 + tig + (e & 1) * 4;
        p2[(((tap * 4 + kk) * 2 + nh) * 32 + lane) * 12 + e] =
            rna_tf32(w2[((size_t)n * 32 + k) * 9 + tap]);
    }
    {   // conv3 full-n: j in 0..1 (nt pair), e in 0..3
        int e = idx & 3, j = (idx >> 2) & 1, lane = (idx >> 3) & 31;
        int kk = (idx >> 8) & 7, tap = idx >> 11;
        int qid = lane >> 2, tig = lane & 3;
        int nt = 2 * j + (e >> 1);
        int k = kk * 8 + tig + (e & 1) * 4;
        int n = nt * 8 + qid;
        p3[((tap * 8 + kk) * 32 + lane) * 12 + j * 4 + e] =
            rna_tf32(w3[((size_t)n * 64 + k) * 9 + tap]);
    }
}

// ---------------- conv1: 1->32 fp32, NHWC out, tf32-rounded ----------------
__global__ void __launch_bounds__(256) conv1_k(
    const float* __restrict__ vs, const float* __restrict__ w,
    const float* __restrict__ bb, float* __restrict__ outp)
{
    __shared__ float sw[288];
    __shared__ float sb[32];
    int tid = threadIdx.x;
    for (int i = tid; i < 288; i += 256) sw[i] = w[i];
    if (tid < 32) sb[tid] = bb[tid];
    __syncthreads();

    int pix = blockIdx.x * 256 + tid;
    int b = pix >> 16, rem = pix & 65535, y = rem >> 8, x = rem & 255;
    float xv[9];
    #pragma unroll
    for (int t = 0; t < 9; t++) {
        int gy = y + t / 3 - 1, gx = x + t % 3 - 1;
        xv[t] = ((unsigned)gy < HGT && (unsigned)gx < WID)
                    ? vs[(b << 16) + (gy << 8) + gx] : 0.f;
    }
    float* op = outp + (size_t)pix * 32;
    #pragma unroll
    for (int c4 = 0; c4 < 8; c4++) {
        float4 o;
        float* po = (float*)&o;
        #pragma unroll
        for (int u = 0; u < 4; u++) {
            int co = c4 * 4 + u;
            float acc = sb[co];
            #pragma unroll
            for (int t = 0; t < 9; t++) acc = fmaf(xv[t], sw[co * 9 + t], acc);
            po[u] = rna_tf32(fmaxf(acc, 0.f));
        }
        *(float4*)(op + c4 * 4) = o;
    }
}

// ---------------- conv2: 32->64 tf32 mma, 1024 thr, n-split (R10, proven 131.7us) ----------------
__global__ void __launch_bounds__(1024, 1) conv2_mma(
    const float* __restrict__ in, const float* __restrict__ wp,
    const float* __restrict__ bias, float* __restrict__ outp)
{
    constexpr int AS = 36;
    extern __shared__ float sm[];
    float* s_act = sm;              // 612*36 = 22032
    float* s_w   = sm + 22032;      // 27648

    const int tid = threadIdx.x;
    const int b   = blockIdx.z;
    const int x0  = blockIdx.x * 32;
    const int y0  = blockIdx.y * 16;

    const float* inb = in + (size_t)b * HW * 32;
    for (int i = tid; i < 612 * 8; i += 1024) {
        int px = i >> 3, j = i & 7;
        int yy = px / 34, xx = px - yy * 34;
        int gy = y0 - 1 + yy, gx = x0 - 1 + xx;
        float4 v = {0.f, 0.f, 0.f, 0.f};
        if ((unsigned)gy < HGT && (unsigned)gx < WID)
            v = *(const float4*)(inb + (size_t)(gy * WID + gx) * 32 + j * 4);
        *(float4*)(s_act + px * AS + j * 4) = v;
    }
    for (int e = tid * 4; e < 27648; e += 4096)
        *(float4*)(s_w + e) = *(const float4*)(wp + e);
    __syncthreads();

    const int warp = tid >> 5, lane = tid & 31;
    const int row = warp >> 1, nh = warp & 1;
    const int qid = lane >> 2, tig = lane & 3;

    float acc[2][4][4];
    #pragma unroll
    for (int mt = 0; mt < 2; mt++)
        #pragma unroll
        for (int nt = 0; nt < 4; nt++)
            #pragma unroll
            for (int u = 0; u < 4; u++) acc[mt][nt][u] = 0.f;

    #pragma unroll 1
    for (int tap = 0; tap < 9; tap++) {
        const float* ab = s_act + ((row + tap / 3) * 34 + tap % 3) * AS + tig;
        const float* wtp = s_w + (((tap * 4) * 2 + nh) * 32 + lane) * 12;
        #pragma unroll
        for (int kk = 0; kk < 4; kk++) {
            uint32_t a[2][4];
            #pragma unroll
            for (int mt = 0; mt < 2; mt++) {
                const float* ap = ab + (qid + mt * 16) * AS + kk * 8;
                a[mt][0] = fau(ap[0]);
                a[mt][2] = fau(ap[4]);
                a[mt][1] = fau(ap[8 * AS]);
                a[mt][3] = fau(ap[8 * AS + 4]);
            }
            const float4* bp = (const float4*)(wtp + kk * 2 * 32 * 12);
            float4 bf0 = bp[0], bf1 = bp[1];
            const float fb[8] = {bf0.x, bf0.y, bf0.z, bf0.w,
                                 bf1.x, bf1.y, bf1.z, bf1.w};
            #pragma unroll
            for (int nt = 0; nt < 4; nt++) {
                uint32_t b0 = fau(fb[nt * 2]);
                uint32_t b1 = fau(fb[nt * 2 + 1]);
                MMA_TF32(acc[0][nt], a[0], b0, b1);
                MMA_TF32(acc[1][nt], a[1], b0, b1);
            }
        }
    }

    float* ob = outp + ((size_t)b * HW + (size_t)(y0 + row) * WID + x0) * 64;
    #pragma unroll
    for (int nt = 0; nt < 4; nt++) {
        int n = nh * 32 + nt * 8 + 2 * tig;
        float bv0 = __ldg(bias + n), bv1 = __ldg(bias + n + 1);
        #pragma unroll
        for (int mt = 0; mt < 2; mt++)
            #pragma unroll
            for (int h = 0; h < 2; h++) {
                int x = qid + mt * 16 + h * 8;
                float v0 = rna_tf32(fmaxf(acc[mt][nt][h * 2 + 0] + bv0, 0.f));
                float v1 = rna_tf32(fmaxf(acc[mt][nt][h * 2 + 1] + bv1, 0.f));
                float2 o = {v0, v1};
                *(float2*)(ob + (size_t)x * 64 + n) = o;
            }
    }
}

// ---------------- conv3: 64->32 tf32 mma, 512 thr, full-n, DOUBLE-BUFFERED prefetch ----------------
// warp = one y-row of 32 px (M=32, 2 m-tiles), full n (4 n-tiles, acc 32).
// (tap,kk) flattened to 24 iters per 3-tap weight chunk; A+B prefetched one iter ahead.
__global__ void __launch_bounds__(512, 1) conv3_mma(
    const float* __restrict__ in, const float* __restrict__ wp,
    const float* __restrict__ bias, float* __restrict__ outp)
{
    constexpr int AS = 68;
    extern __shared__ float sm[];
    float* s_act = sm;              // 612*68 = 41616
    float* s_w   = sm + 41616;      // 3*8*32*12 = 9216

    const int tid = threadIdx.x;
    const int b   = blockIdx.z;
    const int x0  = blockIdx.x * 32;
    const int y0  = blockIdx.y * 16;

    const float* inb = in + (size_t)b * HW * 64;
    for (int i = tid; i < 612 * 16; i += 512) {
        int px = i >> 4, j = i & 15;
        int yy = px / 34, xx = px - yy * 34;
        int gy = y0 - 1 + yy, gx = x0 - 1 + xx;
        float4 v = {0.f, 0.f, 0.f, 0.f};
        if ((unsigned)gy < HGT && (unsigned)gx < WID)
            v = *(const float4*)(inb + (size_t)(gy * WID + gx) * 64 + j * 4);
        *(float4*)(s_act + px * AS + j * 4) = v;
    }

    const int warp = tid >> 5, lane = tid & 31;
    const int qid = lane >> 2, tig = lane & 3;

    float acc[2][4][4];
    #pragma unroll
    for (int mt = 0; mt < 2; mt++)
        #pragma unroll
        for (int nt = 0; nt < 4; nt++)
            #pragma unroll
            for (int u = 0; u < 4; u++) acc[mt][nt][u] = 0.f;

    uint32_t a[2][2][4];   // [buf][mt][frag]
    float    fb[2][8];     // [buf][b-frag]

    #pragma unroll 1
    for (int c = 0; c < 3; c++) {
        if (c) __syncthreads();
        for (int e = tid * 4; e < 9216; e += 2048)
            *(float4*)(s_w + e) = *(const float4*)(wp + c * 9216 + e);
        __syncthreads();

        // prefetch iter 0 of this chunk (tap = c*3, kk = 0)
        {
            const float* ab = s_act + ((warp + c) * 34 + 0) * AS + tig;
            #pragma unroll
            for (int mt = 0; mt < 2; mt++) {
                const float* ap = ab + (qid + mt * 16) * AS;
                a[0][mt][0] = fau(ap[0]);
                a[0][mt][2] = fau(ap[4]);
                a[0][mt][1] = fau(ap[8 * AS]);
                a[0][mt][3] = fau(ap[8 * AS + 4]);
            }
            const float4* bp = (const float4*)(s_w + lane * 12);
            float4 b0 = bp[0], b1 = bp[1];
            fb[0][0] = b0.x; fb[0][1] = b0.y; fb[0][2] = b0.z; fb[0][3] = b0.w;
            fb[0][4] = b1.x; fb[0][5] = b1.y; fb[0][6] = b1.z; fb[0][7] = b1.w;
        }

        #pragma unroll 2
        for (int it = 0; it < 24; it++) {
            const int cur = it & 1;
            if (it < 23) {
                const int nx = it + 1, j3 = nx >> 3, kk = nx & 7;
                const float* ab = s_act + ((warp + c) * 34 + j3) * AS + tig;
                #pragma unroll
                for (int mt = 0; mt < 2; mt++) {
                    const float* ap = ab + (qid + mt * 16) * AS + kk * 8;
                    a[cur ^ 1][mt][0] = fau(ap[0]);
                    a[cur ^ 1][mt][2] = fau(ap[4]);
                    a[cur ^ 1][mt][1] = fau(ap[8 * AS]);
                    a[cur ^ 1][mt][3] = fau(ap[8 * AS + 4]);
                }
                const float4* bp = (const float4*)(s_w + ((j3 * 8 + kk) * 32 + lane) * 12);
                float4 b0 = bp[0], b1 = bp[1];
                fb[cur ^ 1][0] = b0.x; fb[cur ^ 1][1] = b0.y;
                fb[cur ^ 1][2] = b0.z; fb[cur ^ 1][3] = b0.w;
                fb[cur ^ 1][4] = b1.x; fb[cur ^ 1][5] = b1.y;
                fb[cur ^ 1][6] = b1.z; fb[cur ^ 1][7] = b1.w;
            }
            #pragma unroll
            for (int nt = 0; nt < 4; nt++) {
                uint32_t b0 = fau(fb[cur][(nt >> 1) * 4 + (nt & 1) * 2]);
                uint32_t b1 = fau(fb[cur][(nt >> 1) * 4 + (nt & 1) * 2 + 1]);
                MMA_TF32(acc[0][nt], a[cur][0], b0, b1);
                MMA_TF32(acc[1][nt], a[cur][1], b0, b1);
            }
        }
    }

    float* ob = outp + ((size_t)b * HW + (size_t)(y0 + warp) * WID + x0) * 32;
    #pragma unroll
    for (int nt = 0; nt < 4; nt++) {
        int n = nt * 8 + 2 * tig;
        float bv0 = __ldg(bias + n), bv1 = __ldg(bias + n + 1);
        #pragma unroll
        for (int mt = 0; mt < 2; mt++)
            #pragma unroll
            for (int h = 0; h < 2; h++) {
                int x = qid + mt * 16 + h * 8;
                float v0 = fmaxf(acc[mt][nt][h * 2 + 0] + bv0, 0.f);
                float v1 = fmaxf(acc[mt][nt][h * 2 + 1] + bv1, 0.f);
                float2 o = {v0, v1};
                *(float2*)(ob + (size_t)x * 32 + n) = o;
            }
    }
}

// ---------------- conv4: 32->1 fp32 fused final (NHWC in) ----------------
__global__ void __launch_bounds__(256, 1) conv4_k(
    const float* __restrict__ a3, const float* __restrict__ w4,
    const float* __restrict__ b4, const float* __restrict__ sf,
    float* __restrict__ out)
{
    extern __shared__ float sm[];
    float* s_act = sm;                 // 18x18 px * 36
    float* s_w   = sm + 324 * 36;      // [tap][ci]
    const int tid = threadIdx.x;
    const int b = blockIdx.z, x0 = blockIdx.x * 16, y0 = blockIdx.y * 16;

    const float* inb = a3 + (size_t)b * HW * 32;
    for (int i = tid; i < 324 * 8; i += 256) {
        int px = i >> 3, j = i & 7;
        int yy = px / 18, xx = px - yy * 18;
        int gy = y0 - 1 + yy, gx = x0 - 1 + xx;
        float4 v = {0.f, 0.f, 0.f, 0.f};
        if ((unsigned)gy < HGT && (unsigned)gx < WID)
            v = *(const float4*)(inb + (size_t)(gy * WID + gx) * 32 + j * 4);
        *(float4*)(s_act + px * 36 + j * 4) = v;
    }
    for (int i = tid; i < 288; i += 256) s_w[(i % 9) * 32 + i / 9] = w4[i];
    __syncthreads();

    const int py = tid >> 4, px = tid & 15;
    float acc = 0.f;
    #pragma unroll
    for (int t = 0; t < 9; t++) {
        const float* sp = s_act + ((py + t / 3) * 18 + px + t % 3) * 36;
        const float* wpt = s_w + t * 32;
        #pragma unroll
        for (int c4 = 0; c4 < 8; c4++) {
            float4 xv = *(const float4*)(sp + c4 * 4);
            float4 wv = *(const float4*)(wpt + c4 * 4);
            acc = fmaf(xv.x, wv.x, acc);
            acc = fmaf(xv.y, wv.y, acc);
            acc = fmaf(xv.z, wv.z, acc);
            acc = fmaf(xv.w, wv.w, acc);
        }
    }
    float vh = (acc + b4[0]) * sf[0];
    size_t idx = (size_t)b * HW + (size_t)(y0 + py) * WID + (x0 + px);
    out[5 * (size_t)BHW + idx] = vh;
    out[idx] = out[(size_t)BHW + idx] + vh;
}

// ---------------- launch ----------------
extern "C" void kernel_launch(void* const* d_in, const int* in_sizes, int n_in,
                              void* d_out, int out_size)
{
    const float* inputs = (const float*)d_in[0];
    const float* H0     = (const float*)d_in[1];
    const float* C0     = (const float*)d_in[2];
    const float* c2     = (const float*)d_in[3];
    const float* sf     = (const float*)d_in[4];
    const float* w1     = (const float*)d_in[5];
    const float* b1     = (const float*)d_in[6];
    const float* w2     = (const float*)d_in[7];
    const float* b2     = (const float*)d_in[8];
    const float* w3     = (const float*)d_in[9];
    const float* b3     = (const float*)d_in[10];
    const float* w4     = (const float*)d_in[11];
    const float* b4     = (const float*)d_in[12];
    float* out = (float*)d_out;

    float *vs, *actA, *actB, *w2p, *w3p;
    cudaGetSymbolAddress((void**)&vs,   g_vs);
    cudaGetSymbolAddress((void**)&actA, g_actA);
    cudaGetSymbolAddress((void**)&actB, g_actB);
    cudaGetSymbolAddress((void**)&w2p,  g_w2p);
    cudaGetSymbolAddress((void**)&w3p,  g_w3p);

    const int SM2 = (22032 + 27648) * 4;   // 198720
    const int SM3 = (41616 + 9216) * 4;    // 203328
    const int SM4 = (324 * 36 + 288) * 4;  // 47808

    cudaFuncSetAttribute(conv2_mma, cudaFuncAttributeMaxDynamicSharedMemorySize, SM2);
    cudaFuncSetAttribute(conv3_mma, cudaFuncAttributeMaxDynamicSharedMemorySize, SM3);
    cudaFuncSetAttribute(conv4_k,   cudaFuncAttributeMaxDynamicSharedMemorySize, SM4);

    prep_kernel<<<BHW / 256, 256>>>(inputs, H0, C0, c2, sf, out, vs);
    w_pack_k<<<72, 256>>>(w2, w3, w2p, w3p);
    conv1_k<<<BHW / 256, 256>>>(vs, w1, b1, actA);

    dim3 tcg(WID / 32, HGT / 16, BATCH);  // (8, 16, 8)
    conv2_mma<<<tcg, 1024, SM2>>>(actA, w2p, b2, actB);
    conv3_mma<<<tcg,  512, SM3>>>(actB, w3p, b3, actA);

    dim3 c4g(WID / 16, HGT / 16, BATCH);  // (16, 16, 8)
    conv4_k<<<c4g, 256, SM4>>>(actA, w4, b4, sf, out);
}

// round 12
// speedup vs baseline: 1.1822x; 1.1822x over previous
#include <cuda_runtime.h>
#include <cstdint>

#define WID 256
#define HGT 256
#define HW  65536
#define BATCH 8
#define BHW 524288

// ---------------- scratch ----------------
__device__ float g_actA[(size_t)BATCH * HW * 32];  // NHWC 32ch (conv1 out, conv3 out)
__device__ float g_actB[(size_t)BATCH * HW * 64];  // NHWC 64ch (conv2 out)
__device__ float g_w2p[9 * 4 * 2 * 32 * 12];       // conv2 weights lane-packed (nhalf split)
__device__ float g_w3p[2 * 9 * 4 * 32 * 12];       // conv3 weights lane-packed (cin-half, full-n)

// ---------------- helpers ----------------
__device__ __forceinline__ float rna_tf32(float x) {
    uint32_t u;
    asm("cvt.rna.tf32.f32 %0, %1;" : "=r"(u) : "f"(x));
    return __uint_as_float(u);
}
__device__ __forceinline__ uint32_t fau(float x) { return __float_as_uint(x); }

#define MMA_TF32(d, a, b0, b1) \
    asm volatile("mma.sync.aligned.m16n8k8.row.col.f32.tf32.tf32.f32 " \
        "{%0,%1,%2,%3}, {%4,%5,%6,%7}, {%8,%9}, {%0,%1,%2,%3};" \
        : "+f"((d)[0]), "+f"((d)[1]), "+f"((d)[2]), "+f"((d)[3]) \
        : "r"((a)[0]), "r"((a)[1]), "r"((a)[2]), "r"((a)[3]), "r"(b0), "r"(b1))

// ---------------- weight pack ----------------
// conv2: R10 nh-split layout (proven). conv3: cin-half h, full-n, stride-12.
__global__ void __launch_bounds__(256) w_pack_k(
    const float* __restrict__ w2, const float* __restrict__ w3,
    float* __restrict__ p2, float* __restrict__ p3)
{
    int idx = blockIdx.x * 256 + threadIdx.x;   // < 18432
    {   // conv2: e in 0..7 -> nt_local = e>>1, ksel = e&1
        int e = idx & 7, lane = (idx >> 3) & 31;
        int nh = (idx >> 8) & 1, kk = (idx >> 9) & 3, tap = idx >> 11;
        int qid = lane >> 2, tig = lane & 3;
        int n = (nh * 4 + (e >> 1)) * 8 + qid;
        int k = kk * 8 + tig + (e & 1) * 4;
        p2[(((tap * 4 + kk) * 2 + nh) * 32 + lane) * 12 + e] =
            rna_tf32(w2[((size_t)n * 32 + k) * 9 + tap]);
    }
    {   // conv3: h = cin half, full-n (j = nt pair, e -> nt/ksel)
        int e = idx & 3, j = (idx >> 2) & 1, lane = (idx >> 3) & 31;
        int kk = (idx >> 8) & 3, t9 = idx >> 10;      // 0..17
        int tap = t9 % 9, h = t9 / 9;
        int qid = lane >> 2, tig = lane & 3;
        int nt = 2 * j + (e >> 1);
        int n = nt * 8 + qid;
        int k = h * 32 + kk * 8 + tig + (e & 1) * 4;
        p3[(((h * 9 + tap) * 4 + kk) * 32 + lane) * 12 + j * 4 + e] =
            rna_tf32(w3[((size_t)n * 64 + k) * 9 + tap]);
    }
}

// ---------------- fused prep + conv1 ----------------
// 16x16 px tile. Computes lap/H/V/C_new AND conv1 (1->32, NHWC, tf32-rounded)
// from smem tiles; vs never touches gmem.
// out sections: [0)outputs [1)H [2..3)C_new [4)V [5)V_hat
__global__ void __launch_bounds__(256) fuse_pc1_k(
    const float* __restrict__ inp, const float* __restrict__ H0,
    const float* __restrict__ C0, const float* __restrict__ c2,
    const float* __restrict__ sf, const float* __restrict__ w1,
    const float* __restrict__ b1, float* __restrict__ out,
    float* __restrict__ actA)
{
    __shared__ float s_in[324];   // 18x18 inputs (0 outside image)
    __shared__ float s_vs[324];   // 18x18 V/sf   (0 outside image)
    __shared__ float sw[288];
    __shared__ float sb[32];

    const int tid = threadIdx.x;
    const int b = blockIdx.z, x0 = blockIdx.x * 16, y0 = blockIdx.y * 16;

    for (int i = tid; i < 288; i += 256) sw[i] = w1[i];   // [co][tap]
    if (tid < 32) sb[tid] = b1[tid];
    const float sfv = sf[0];

    for (int i = tid; i < 324; i += 256) {
        int yy = i / 18, xx = i - yy * 18;
        int gy = y0 - 1 + yy, gx = x0 - 1 + xx;
        float iv = 0.f, vsv = 0.f;
        if ((unsigned)gy < HGT && (unsigned)gx < WID) {
            int gidx = (b << 16) + (gy << 8) + gx;
            iv  = inp[gidx];
            vsv = (iv - H0[gidx]) / sfv;
        }
        s_in[i] = iv;
        s_vs[i] = vsv;
    }
    __syncthreads();

    const int py = tid >> 4, px = tid & 15;
    const int y = y0 + py, x = x0 + px;
    const int si = (py + 1) * 18 + px + 1;
    const int rem = (y << 8) + x;
    const int idx = (b << 16) + rem;

    float cc  = s_in[si];
    float lap = s_in[si - 18] + s_in[si + 18] + s_in[si - 1] + s_in[si + 1] - 4.f * cc;
    float c0v = C0[(size_t)b * 2 * HW + rem];
    float Hv  = 2.f * cc - c0v + c2[0] * lap;
    float V   = cc - H0[idx];

    out[(size_t)BHW + idx]     = Hv;
    out[4 * (size_t)BHW + idx] = V;
    out[2 * (size_t)BHW + (size_t)b * 2 * HW + rem]      = cc;
    out[2 * (size_t)BHW + (size_t)b * 2 * HW + HW + rem] = c0v;

    // conv1 from vs tile
    float xv[9];
    #pragma unroll
    for (int t = 0; t < 9; t++)
        xv[t] = s_vs[(py + t / 3) * 18 + px + t % 3];

    float* op = actA + (size_t)idx * 32;
    #pragma unroll
    for (int c4 = 0; c4 < 8; c4++) {
        float4 o;
        float* po = (float*)&o;
        #pragma unroll
        for (int u = 0; u < 4; u++) {
            int co = c4 * 4 + u;
            float acc = sb[co];
            #pragma unroll
            for (int t = 0; t < 9; t++) acc = fmaf(xv[t], sw[co * 9 + t], acc);
            po[u] = rna_tf32(fmaxf(acc, 0.f));
        }
        *(float4*)(op + c4 * 4) = o;
    }
}

// ---------------- conv2: 32->64 tf32 mma, 1024 thr, n-split (R10, proven 131.7us) ----------------
__global__ void __launch_bounds__(1024, 1) conv2_mma(
    const float* __restrict__ in, const float* __restrict__ wp,
    const float* __restrict__ bias, float* __restrict__ outp)
{
    constexpr int AS = 36;
    extern __shared__ float sm[];
    float* s_act = sm;              // 612*36 = 22032
    float* s_w   = sm + 22032;      // 27648

    const int tid = threadIdx.x;
    const int b   = blockIdx.z;
    const int x0  = blockIdx.x * 32;
    const int y0  = blockIdx.y * 16;

    const float* inb = in + (size_t)b * HW * 32;
    for (int i = tid; i < 612 * 8; i += 1024) {
        int px = i >> 3, j = i & 7;
        int yy = px / 34, xx = px - yy * 34;
        int gy = y0 - 1 + yy, gx = x0 - 1 + xx;
        float4 v = {0.f, 0.f, 0.f, 0.f};
        if ((unsigned)gy < HGT && (unsigned)gx < WID)
            v = *(const float4*)(inb + (size_t)(gy * WID + gx) * 32 + j * 4);
        *(float4*)(s_act + px * AS + j * 4) = v;
    }
    for (int e = tid * 4; e < 27648; e += 4096)
        *(float4*)(s_w + e) = *(const float4*)(wp + e);
    __syncthreads();

    const int warp = tid >> 5, lane = tid & 31;
    const int row = warp >> 1, nh = warp & 1;
    const int qid = lane >> 2, tig = lane & 3;

    float acc[2][4][4];
    #pragma unroll
    for (int mt = 0; mt < 2; mt++)
        #pragma unroll
        for (int nt = 0; nt < 4; nt++)
            #pragma unroll
            for (int u = 0; u < 4; u++) acc[mt][nt][u] = 0.f;

    #pragma unroll 1
    for (int tap = 0; tap < 9; tap++) {
        const float* ab = s_act + ((row + tap / 3) * 34 + tap % 3) * AS + tig;
        const float* wtp = s_w + (((tap * 4) * 2 + nh) * 32 + lane) * 12;
        #pragma unroll
        for (int kk = 0; kk < 4; kk++) {
            uint32_t a[2][4];
            #pragma unroll
            for (int mt = 0; mt < 2; mt++) {
                const float* ap = ab + (qid + mt * 16) * AS + kk * 8;
                a[mt][0] = fau(ap[0]);
                a[mt][2] = fau(ap[4]);
                a[mt][1] = fau(ap[8 * AS]);
                a[mt][3] = fau(ap[8 * AS + 4]);
            }
            const float4* bp = (const float4*)(wtp + kk * 2 * 32 * 12);
            float4 bf0 = bp[0], bf1 = bp[1];
            const float fb[8] = {bf0.x, bf0.y, bf0.z, bf0.w,
                                 bf1.x, bf1.y, bf1.z, bf1.w};
            #pragma unroll
            for (int nt = 0; nt < 4; nt++) {
                uint32_t b0 = fau(fb[nt * 2]);
                uint32_t b1 = fau(fb[nt * 2 + 1]);
                MMA_TF32(acc[0][nt], a[0], b0, b1);
                MMA_TF32(acc[1][nt], a[1], b0, b1);
            }
        }
    }

    float* ob = outp + ((size_t)b * HW + (size_t)(y0 + row) * WID + x0) * 64;
    #pragma unroll
    for (int nt = 0; nt < 4; nt++) {
        int n = nh * 32 + nt * 8 + 2 * tig;
        float bv0 = __ldg(bias + n), bv1 = __ldg(bias + n + 1);
        #pragma unroll
        for (int mt = 0; mt < 2; mt++)
            #pragma unroll
            for (int h = 0; h < 2; h++) {
                int x = qid + mt * 16 + h * 8;
                float v0 = rna_tf32(fmaxf(acc[mt][nt][h * 2 + 0] + bv0, 0.f));
                float v1 = rna_tf32(fmaxf(acc[mt][nt][h * 2 + 1] + bv1, 0.f));
                float2 o = {v0, v1};
                *(float2*)(ob + (size_t)x * 64 + n) = o;
            }
    }
}

// ---------------- conv3: 64->32 tf32 mma, 512 thr, 2 CTAs/SM, cin-halved act ----------------
// warp = one y-row of 32 px (M=32), full n (N=32, 4 nt, acc=32).
// Act staged 32 channels at a time (AS=36); weights in 3-tap chunks.
__global__ void __launch_bounds__(512, 2) conv3_mma(
    const float* __restrict__ in, const float* __restrict__ wp,
    const float* __restrict__ bias, float* __restrict__ outp)
{
    constexpr int AS = 36;
    extern __shared__ float sm[];
    float* s_act = sm;              // 612*36 = 22032
    float* s_w   = sm + 22032;      // 3*4*32*12 = 4608

    const int tid = threadIdx.x;
    const int b   = blockIdx.z;
    const int x0  = blockIdx.x * 32;
    const int y0  = blockIdx.y * 16;

    const float* inb = in + (size_t)b * HW * 64;
    const int warp = tid >> 5, lane = tid & 31;
    const int qid = lane >> 2, tig = lane & 3;

    float acc[2][4][4];
    #pragma unroll
    for (int mt = 0; mt < 2; mt++)
        #pragma unroll
        for (int nt = 0; nt < 4; nt++)
            #pragma unroll
            for (int u = 0; u < 4; u++) acc[mt][nt][u] = 0.f;

    #pragma unroll 1
    for (int h = 0; h < 2; h++) {
        if (h) __syncthreads();  // previous half's MMAs done before act overwrite
        for (int i = tid; i < 612 * 8; i += 512) {
            int px = i >> 3, j = i & 7;
            int yy = px / 34, xx = px - yy * 34;
            int gy = y0 - 1 + yy, gx = x0 - 1 + xx;
            float4 v = {0.f, 0.f, 0.f, 0.f};
            if ((unsigned)gy < HGT && (unsigned)gx < WID)
                v = *(const float4*)(inb + (size_t)(gy * WID + gx) * 64 + h * 32 + j * 4);
            *(float4*)(s_act + px * AS + j * 4) = v;
        }
        #pragma unroll 1
        for (int c = 0; c < 3; c++) {
            __syncthreads();  // act ready / previous chunk's MMAs done
            for (int e = tid * 4; e < 4608; e += 2048)
                *(float4*)(s_w + e) =
                    *(const float4*)(wp + (size_t)(h * 9 + c * 3) * 1536 + e);
            __syncthreads();
            #pragma unroll
            for (int t3 = 0; t3 < 3; t3++) {
                const int tap = c * 3 + t3;
                const float* ab = s_act + ((warp + tap / 3) * 34 + tap % 3) * AS + tig;
                const float* wtp = s_w + (t3 * 4 * 32 + lane) * 12;
                #pragma unroll
                for (int kk = 0; kk < 4; kk++) {
                    uint32_t a[2][4];
                    #pragma unroll
                    for (int mt = 0; mt < 2; mt++) {
                        const float* ap = ab + (qid + mt * 16) * AS + kk * 8;
                        a[mt][0] = fau(ap[0]);
                        a[mt][2] = fau(ap[4]);
                        a[mt][1] = fau(ap[8 * AS]);
                        a[mt][3] = fau(ap[8 * AS + 4]);
                    }
                    const float4* bp = (const float4*)(wtp + kk * 32 * 12);
                    float4 bf0 = bp[0], bf1 = bp[1];
                    const float fb[8] = {bf0.x, bf0.y, bf0.z, bf0.w,
                                         bf1.x, bf1.y, bf1.z, bf1.w};
                    #pragma unroll
                    for (int nt = 0; nt < 4; nt++) {
                        uint32_t b0 = fau(fb[(nt >> 1) * 4 + (nt & 1) * 2]);
                        uint32_t b1 = fau(fb[(nt >> 1) * 4 + (nt & 1) * 2 + 1]);
                        MMA_TF32(acc[0][nt], a[0], b0, b1);
                        MMA_TF32(acc[1][nt], a[1], b0, b1);
                    }
                }
            }
        }
    }

    float* ob = outp + ((size_t)b * HW + (size_t)(y0 + warp) * WID + x0) * 32;
    #pragma unroll
    for (int nt = 0; nt < 4; nt++) {
        int n = nt * 8 + 2 * tig;
        float bv0 = __ldg(bias + n), bv1 = __ldg(bias + n + 1);
        #pragma unroll
        for (int mt = 0; mt < 2; mt++)
            #pragma unroll
            for (int hh = 0; hh < 2; hh++) {
                int x = qid + mt * 16 + hh * 8;
                float v0 = fmaxf(acc[mt][nt][hh * 2 + 0] + bv0, 0.f);
                float v1 = fmaxf(acc[mt][nt][hh * 2 + 1] + bv1, 0.f);
                float2 o = {v0, v1};
                *(float2*)(ob + (size_t)x * 32 + n) = o;
            }
    }
}

// ---------------- conv4: 32->1 fp32 fused final (NHWC in) ----------------
__global__ void __launch_bounds__(256, 1) conv4_k(
    const float* __restrict__ a3, const float* __restrict__ w4,
    const float* __restrict__ b4, const float* __restrict__ sf,
    float* __restrict__ out)
{
    extern __shared__ float sm[];
    float* s_act = sm;                 // 18x18 px * 36
    float* s_w   = sm + 324 * 36;      // [tap][ci]
    const int tid = threadIdx.x;
    const int b = blockIdx.z, x0 = blockIdx.x * 16, y0 = blockIdx.y * 16;

    const float* inb = a3 + (size_t)b * HW * 32;
    for (int i = tid; i < 324 * 8; i += 256) {
        int px = i >> 3, j = i & 7;
        int yy = px / 18, xx = px - yy * 18;
        int gy = y0 - 1 + yy, gx = x0 - 1 + xx;
        float4 v = {0.f, 0.f, 0.f, 0.f};
        if ((unsigned)gy < HGT && (unsigned)gx < WID)
            v = *(const float4*)(inb + (size_t)(gy * WID + gx) * 32 + j * 4);
        *(float4*)(s_act + px * 36 + j * 4) = v;
    }
    for (int i = tid; i < 288; i += 256) s_w[(i % 9) * 32 + i / 9] = w4[i];
    __syncthreads();

    const int py = tid >> 4, px = tid & 15;
    float acc = 0.f;
    #pragma unroll
    for (int t = 0; t < 9; t++) {
        const float* sp = s_act + ((py + t / 3) * 18 + px + t % 3) * 36;
        const float* wpt = s_w + t * 32;
        #pragma unroll
        for (int c4 = 0; c4 < 8; c4++) {
            float4 xv = *(const float4*)(sp + c4 * 4);
            float4 wv = *(const float4*)(wpt + c4 * 4);
            acc = fmaf(xv.x, wv.x, acc);
            acc = fmaf(xv.y, wv.y, acc);
            acc = fmaf(xv.z, wv.z, acc);
            acc = fmaf(xv.w, wv.w, acc);
        }
    }
    float vh = (acc + b4[0]) * sf[0];
    size_t idx = (size_t)b * HW + (size_t)(y0 + py) * WID + (x0 + px);
    out[5 * (size_t)BHW + idx] = vh;
    out[idx] = out[(size_t)BHW + idx] + vh;
}

// ---------------- launch ----------------
extern "C" void kernel_launch(void* const* d_in, const int* in_sizes, int n_in,
                              void* d_out, int out_size)
{
    const float* inputs = (const float*)d_in[0];
    const float* H0     = (const float*)d_in[1];
    const float* C0     = (const float*)d_in[2];
    const float* c2     = (const float*)d_in[3];
    const float* sf     = (const float*)d_in[4];
    const float* w1     = (const float*)d_in[5];
    const float* b1     = (const float*)d_in[6];
    const float* w2     = (const float*)d_in[7];
    const float* b2     = (const float*)d_in[8];
    const float* w3     = (const float*)d_in[9];
    const float* b3     = (const float*)d_in[10];
    const float* w4     = (const float*)d_in[11];
    const float* b4     = (const float*)d_in[12];
    float* out = (float*)d_out;

    float *actA, *actB, *w2p, *w3p;
    cudaGetSymbolAddress((void**)&actA, g_actA);
    cudaGetSymbolAddress((void**)&actB, g_actB);
    cudaGetSymbolAddress((void**)&w2p,  g_w2p);
    cudaGetSymbolAddress((void**)&w3p,  g_w3p);

    const int SM2 = (22032 + 27648) * 4;   // 198720
    const int SM3 = (22032 + 4608) * 4;    // 106560 -> 2 CTAs/SM
    const int SM4 = (324 * 36 + 288) * 4;  // 47808

    cudaFuncSetAttribute(conv2_mma, cudaFuncAttributeMaxDynamicSharedMemorySize, SM2);
    cudaFuncSetAttribute(conv3_mma, cudaFuncAttributeMaxDynamicSharedMemorySize, SM3);
    cudaFuncSetAttribute(conv4_k,   cudaFuncAttributeMaxDynamicSharedMemorySize, SM4);

    w_pack_k<<<72, 256>>>(w2, w3, w2p, w3p);

    dim3 pg(WID / 16, HGT / 16, BATCH);   // (16, 16, 8)
    fuse_pc1_k<<<pg, 256>>>(inputs, H0, C0, c2, sf, w1, b1, out, actA);

    dim3 tcg(WID / 32, HGT / 16, BATCH);  // (8, 16, 8)
    conv2_mma<<<tcg, 1024, SM2>>>(actA, w2p, b2, actB);
    conv3_mma<<<tcg,  512, SM3>>>(actB, w3p, b3, actA);

    conv4_k<<<pg, 256, SM4>>>(actA, w4, b4, sf, out);
}

// round 13
// speedup vs baseline: 1.8242x; 1.5430x over previous
#include <cuda_runtime.h>
#include <cuda_fp16.h>
#include <cstdint>

#define WID 256
#define HGT 256
#define HW  65536
#define BATCH 8
#define BHW 524288

// ---------------- scratch ----------------
__device__ __half g_actAh[(size_t)BATCH * HW * 32];  // conv1 out (half, NHWC)
__device__ __half g_actBh[(size_t)BATCH * HW * 64];  // conv2 out (half, NHWC)
__device__ float  g_actC[(size_t)BATCH * HW * 32];   // conv3 out (float, NHWC)
__device__ __half g_w2p[9 * 2 * 2 * 512];            // conv2 w packed (tap,kk,nh) 1KB blocks
__device__ __half g_w3p[2 * 9 * 2 * 2 * 512];        // conv3 w packed (h,tap,kk) 1KB blocks

// ---------------- helpers ----------------
__device__ __forceinline__ uint32_t fau(float x) { return __float_as_uint(x); }

#define MMA_F16(d, a, b0, b1) \
    asm volatile("mma.sync.aligned.m16n8k16.row.col.f32.f16.f16.f32 " \
        "{%0,%1,%2,%3}, {%4,%5,%6,%7}, {%8,%9}, {%0,%1,%2,%3};" \
        : "+f"((d)[0]), "+f"((d)[1]), "+f"((d)[2]), "+f"((d)[3]) \
        : "r"((a)[0]), "r"((a)[1]), "r"((a)[2]), "r"((a)[3]), "r"(b0), "r"(b1))

// ---------------- weight pack: fp16, exact fragment order ----------------
// block layout per (tap,kk[,nh]) = 1024B: blk0 512B then blk1 512B; each blk:
// lane*16B = 4 u32 = {nt.b0, nt.b1, (nt+1).b0, (nt+1).b1}, nt = blk*2.
__global__ void __launch_bounds__(256) w_pack_k(
    const float* __restrict__ w2, const float* __restrict__ w3,
    __half* __restrict__ p2, __half* __restrict__ p3)
{
    int idx = blockIdx.x * 256 + threadIdx.x;   // < 36864
    if (idx < 18432) {   // conv2: nh-split (N=32 per warp)
        int e = idx & 7, lane = (idx >> 3) & 31;
        int blk = (idx >> 8) & 1, nh = (idx >> 9) & 1;
        int kk = (idx >> 10) & 1, tap = idx >> 11;      // 0..8
        int qid = lane >> 2, tig = lane & 3;
        int nt = blk * 2 + (e >> 2), breg = (e >> 1) & 1, lo = e & 1;
        int k = kk * 16 + breg * 8 + 2 * tig + lo;
        int n = nh * 32 + nt * 8 + qid;
        p2[((((tap * 2 + kk) * 2 + nh) * 2 + blk) * 32 + lane) * 8 + e] =
            __float2half_rn(w2[((size_t)n * 32 + k) * 9 + tap]);
    }
    {   // conv3: full-n, cin-half h
        int h = idx / 18432, r = idx - h * 18432;
        int tap = r / 2048, r2 = r - tap * 2048;
        int kk = (r2 >> 10) & 1, blk = (r2 >> 9) & 1;
        int lane = (r2 >> 3) & 31, e = r2 & 7;
        int qid = lane >> 2, tig = lane & 3;
        int nt = blk * 2 + (e >> 2), breg = (e >> 1) & 1, lo = e & 1;
        int k = h * 32 + kk * 16 + breg * 8 + 2 * tig + lo;
        int n = nt * 8 + qid;
        p3[(size_t)h * 18432 +
           (((tap * 2 + kk) * 2 + blk) * 32 + lane) * 8 + e] =
            __float2half_rn(w3[((size_t)n * 64 + k) * 9 + tap]);
    }
}

// ---------------- fused prep + conv1 (half out) ----------------
__global__ void __launch_bounds__(256) fuse_pc1_k(
    const float* __restrict__ inp, const float* __restrict__ H0,
    const float* __restrict__ C0, const float* __restrict__ c2,
    const float* __restrict__ sf, const float* __restrict__ w1,
    const float* __restrict__ b1, float* __restrict__ out,
    __half* __restrict__ actA)
{
    __shared__ float s_in[324];
    __shared__ float s_vs[324];
    __shared__ float sw[288];
    __shared__ float sb[32];

    const int tid = threadIdx.x;
    const int b = blockIdx.z, x0 = blockIdx.x * 16, y0 = blockIdx.y * 16;

    for (int i = tid; i < 288; i += 256) sw[i] = w1[i];
    if (tid < 32) sb[tid] = b1[tid];
    const float sfv = sf[0];

    for (int i = tid; i < 324; i += 256) {
        int yy = i / 18, xx = i - yy * 18;
        int gy = y0 - 1 + yy, gx = x0 - 1 + xx;
        float iv = 0.f, vsv = 0.f;
        if ((unsigned)gy < HGT && (unsigned)gx < WID) {
            int gidx = (b << 16) + (gy << 8) + gx;
            iv  = inp[gidx];
            vsv = (iv - H0[gidx]) / sfv;
        }
        s_in[i] = iv;
        s_vs[i] = vsv;
    }
    __syncthreads();

    const int py = tid >> 4, px = tid & 15;
    const int y = y0 + py, x = x0 + px;
    const int si = (py + 1) * 18 + px + 1;
    const int rem = (y << 8) + x;
    const int idx = (b << 16) + rem;

    float cc  = s_in[si];
    float lap = s_in[si - 18] + s_in[si + 18] + s_in[si - 1] + s_in[si + 1] - 4.f * cc;
    float c0v = C0[(size_t)b * 2 * HW + rem];
    float Hv  = 2.f * cc - c0v + c2[0] * lap;
    float V   = cc - H0[idx];

    out[(size_t)BHW + idx]     = Hv;
    out[4 * (size_t)BHW + idx] = V;
    out[2 * (size_t)BHW + (size_t)b * 2 * HW + rem]      = cc;
    out[2 * (size_t)BHW + (size_t)b * 2 * HW + HW + rem] = c0v;

    float xv[9];
    #pragma unroll
    for (int t = 0; t < 9; t++)
        xv[t] = s_vs[(py + t / 3) * 18 + px + t % 3];

    __half2* op = (__half2*)(actA + (size_t)idx * 32);
    #pragma unroll
    for (int c2i = 0; c2i < 16; c2i++) {
        float v[2];
        #pragma unroll
        for (int u = 0; u < 2; u++) {
            int co = c2i * 2 + u;
            float acc = sb[co];
            #pragma unroll
            for (int t = 0; t < 9; t++) acc = fmaf(xv[t], sw[co * 9 + t], acc);
            v[u] = fmaxf(acc, 0.f);
        }
        op[c2i] = __floats2half2_rn(v[0], v[1]);
    }
}

// ---------------- conv2: 32->64 fp16 mma k16, 1024 thr, n-split warps ----------------
__global__ void __launch_bounds__(1024, 1) conv2_mma(
    const __half* __restrict__ in, const __half* __restrict__ wp,
    const float* __restrict__ bias, __half* __restrict__ outp)
{
    constexpr int AS = 40;  // halves per pixel (32 + pad)
    extern __shared__ char smraw[];
    __half* s_act = (__half*)smraw;          // 612*40*2 = 48960 B
    char*   s_wb  = smraw + 48960;           // 36864 B

    const int tid = threadIdx.x;
    const int b   = blockIdx.z;
    const int x0  = blockIdx.x * 32;
    const int y0  = blockIdx.y * 16;

    const __half* inb = in + (size_t)b * HW * 32;
    for (int i = tid; i < 612 * 4; i += 1024) {
        int px = i >> 2, j = i & 3;
        int yy = px / 34, xx = px - yy * 34;
        int gy = y0 - 1 + yy, gx = x0 - 1 + xx;
        uint4 v = {0u, 0u, 0u, 0u};
        if ((unsigned)gy < HGT && (unsigned)gx < WID)
            v = *(const uint4*)(inb + (size_t)(gy * WID + gx) * 32 + j * 8);
        *(uint4*)(s_act + px * AS + j * 8) = v;
    }
    for (int i = tid; i < 2304; i += 1024)
        ((uint4*)s_wb)[i] = ((const uint4*)wp)[i];
    __syncthreads();

    const int warp = tid >> 5, lane = tid & 31;
    const int row = warp >> 1, nh = warp & 1;
    const int qid = lane >> 2, tig = lane & 3;

    float acc[2][4][4];
    #pragma unroll
    for (int mt = 0; mt < 2; mt++)
        #pragma unroll
        for (int nt = 0; nt < 4; nt++)
            #pragma unroll
            for (int u = 0; u < 4; u++) acc[mt][nt][u] = 0.f;

    #pragma unroll 1
    for (int tap = 0; tap < 9; tap++) {
        const int pxb = (row + tap / 3) * 34 + tap % 3 + qid;
        #pragma unroll
        for (int kk = 0; kk < 2; kk++) {
            uint32_t a[2][4];
            #pragma unroll
            for (int mt = 0; mt < 2; mt++) {
                const __half* ap = s_act + (pxb + mt * 16) * AS + kk * 16 + 2 * tig;
                a[mt][0] = *(const uint32_t*)(ap);
                a[mt][1] = *(const uint32_t*)(ap + 8 * AS);
                a[mt][2] = *(const uint32_t*)(ap + 8);
                a[mt][3] = *(const uint32_t*)(ap + 8 * AS + 8);
            }
            const char* wb = s_wb + ((tap * 2 + kk) * 2 + nh) * 1024 + lane * 16;
            uint4 B0 = *(const uint4*)wb;
            uint4 B1 = *(const uint4*)(wb + 512);
            #pragma unroll
            for (int mt = 0; mt < 2; mt++) {
                MMA_F16(acc[mt][0], a[mt], B0.x, B0.y);
                MMA_F16(acc[mt][1], a[mt], B0.z, B0.w);
                MMA_F16(acc[mt][2], a[mt], B1.x, B1.y);
                MMA_F16(acc[mt][3], a[mt], B1.z, B1.w);
            }
        }
    }

    __half* ob = outp + ((size_t)b * HW + (size_t)(y0 + row) * WID + x0) * 64;
    #pragma unroll
    for (int nt = 0; nt < 4; nt++) {
        int n = nh * 32 + nt * 8 + 2 * tig;
        float bv0 = __ldg(bias + n), bv1 = __ldg(bias + n + 1);
        #pragma unroll
        for (int mt = 0; mt < 2; mt++)
            #pragma unroll
            for (int hh = 0; hh < 2; hh++) {
                int x = qid + mt * 16 + hh * 8;
                float v0 = fmaxf(acc[mt][nt][hh * 2 + 0] + bv0, 0.f);
                float v1 = fmaxf(acc[mt][nt][hh * 2 + 1] + bv1, 0.f);
                *(__half2*)(ob + (size_t)x * 64 + n) = __floats2half2_rn(v0, v1);
            }
    }
}

// ---------------- conv3: 64->32 fp16 mma k16, 512 thr, 2 CTAs/SM, cin-halved ----------------
__global__ void __launch_bounds__(512, 2) conv3_mma(
    const __half* __restrict__ in, const __half* __restrict__ wp,
    const float* __restrict__ bias, float* __restrict__ outp)
{
    constexpr int AS = 40;
    extern __shared__ char smraw[];
    __half* s_act = (__half*)smraw;          // 48960 B
    char*   s_wb  = smraw + 48960;           // 18432 B

    const int tid = threadIdx.x;
    const int b   = blockIdx.z;
    const int x0  = blockIdx.x * 32;
    const int y0  = blockIdx.y * 16;

    const __half* inb = in + (size_t)b * HW * 64;
    const int warp = tid >> 5, lane = tid & 31;
    const int qid = lane >> 2, tig = lane & 3;

    float acc[2][4][4];
    #pragma unroll
    for (int mt = 0; mt < 2; mt++)
        #pragma unroll
        for (int nt = 0; nt < 4; nt++)
            #pragma unroll
            for (int u = 0; u < 4; u++) acc[mt][nt][u] = 0.f;

    #pragma unroll 1
    for (int h = 0; h < 2; h++) {
        if (h) __syncthreads();
        for (int i = tid; i < 612 * 4; i += 512) {
            int px = i >> 2, j = i & 3;
            int yy = px / 34, xx = px - yy * 34;
            int gy = y0 - 1 + yy, gx = x0 - 1 + xx;
            uint4 v = {0u, 0u, 0u, 0u};
            if ((unsigned)gy < HGT && (unsigned)gx < WID)
                v = *(const uint4*)(inb + (size_t)(gy * WID + gx) * 64 + h * 32 + j * 8);
            *(uint4*)(s_act + px * AS + j * 8) = v;
        }
        for (int i = tid; i < 1152; i += 512)
            ((uint4*)s_wb)[i] = ((const uint4*)(wp + (size_t)h * 18432))[i];
        __syncthreads();

        #pragma unroll 1
        for (int tap = 0; tap < 9; tap++) {
            const int pxb = (warp + tap / 3) * 34 + tap % 3 + qid;
            #pragma unroll
            for (int kk = 0; kk < 2; kk++) {
                uint32_t a[2][4];
                #pragma unroll
                for (int mt = 0; mt < 2; mt++) {
                    const __half* ap = s_act + (pxb + mt * 16) * AS + kk * 16 + 2 * tig;
                    a[mt][0] = *(const uint32_t*)(ap);
                    a[mt][1] = *(const uint32_t*)(ap + 8 * AS);
                    a[mt][2] = *(const uint32_t*)(ap + 8);
                    a[mt][3] = *(const uint32_t*)(ap + 8 * AS + 8);
                }
                const char* wb = s_wb + (tap * 2 + kk) * 1024 + lane * 16;
                uint4 B0 = *(const uint4*)wb;
                uint4 B1 = *(const uint4*)(wb + 512);
                #pragma unroll
                for (int mt = 0; mt < 2; mt++) {
                    MMA_F16(acc[mt][0], a[mt], B0.x, B0.y);
                    MMA_F16(acc[mt][1], a[mt], B0.z, B0.w);
                    MMA_F16(acc[mt][2], a[mt], B1.x, B1.y);
                    MMA_F16(acc[mt][3], a[mt], B1.z, B1.w);
                }
            }
        }
    }

    float* ob = outp + ((size_t)b * HW + (size_t)(y0 + warp) * WID + x0) * 32;
    #pragma unroll
    for (int nt = 0; nt < 4; nt++) {
        int n = nt * 8 + 2 * tig;
        float bv0 = __ldg(bias + n), bv1 = __ldg(bias + n + 1);
        #pragma unroll
        for (int mt = 0; mt < 2; mt++)
            #pragma unroll
            for (int hh = 0; hh < 2; hh++) {
                int x = qid + mt * 16 + hh * 8;
                float v0 = fmaxf(acc[mt][nt][hh * 2 + 0] + bv0, 0.f);
                float v1 = fmaxf(acc[mt][nt][hh * 2 + 1] + bv1, 0.f);
                float2 o = {v0, v1};
                *(float2*)(ob + (size_t)x * 32 + n) = o;
            }
    }
}

// ---------------- conv4: 32->1 fp32 fused final ----------------
__global__ void __launch_bounds__(256, 1) conv4_k(
    const float* __restrict__ a3, const float* __restrict__ w4,
    const float* __restrict__ b4, const float* __restrict__ sf,
    float* __restrict__ out)
{
    extern __shared__ float sm[];
    float* s_act = sm;                 // 18x18 px * 36
    float* s_w   = sm + 324 * 36;
    const int tid = threadIdx.x;
    const int b = blockIdx.z, x0 = blockIdx.x * 16, y0 = blockIdx.y * 16;

    const float* inb = a3 + (size_t)b * HW * 32;
    for (int i = tid; i < 324 * 8; i += 256) {
        int px = i >> 3, j = i & 7;
        int yy = px / 18, xx = px - yy * 18;
        int gy = y0 - 1 + yy, gx = x0 - 1 + xx;
        float4 v = {0.f, 0.f, 0.f, 0.f};
        if ((unsigned)gy < HGT && (unsigned)gx < WID)
            v = *(const float4*)(inb + (size_t)(gy * WID + gx) * 32 + j * 4);
        *(float4*)(s_act + px * 36 + j * 4) = v;
    }
    for (int i = tid; i < 288; i += 256) s_w[(i % 9) * 32 + i / 9] = w4[i];
    __syncthreads();

    const int py = tid >> 4, px = tid & 15;
    float acc = 0.f;
    #pragma unroll
    for (int t = 0; t < 9; t++) {
        const float* sp = s_act + ((py + t / 3) * 18 + px + t % 3) * 36;
        const float* wpt = s_w + t * 32;
        #pragma unroll
        for (int c4 = 0; c4 < 8; c4++) {
            float4 xv = *(const float4*)(sp + c4 * 4);
            float4 wv = *(const float4*)(wpt + c4 * 4);
            acc = fmaf(xv.x, wv.x, acc);
            acc = fmaf(xv.y, wv.y, acc);
            acc = fmaf(xv.z, wv.z, acc);
            acc = fmaf(xv.w, wv.w, acc);
        }
    }
    float vh = (acc + b4[0]) * sf[0];
    size_t idx = (size_t)b * HW + (size_t)(y0 + py) * WID + (x0 + px);
    out[5 * (size_t)BHW + idx] = vh;
    out[idx] = out[(size_t)BHW + idx] + vh;
}

// ---------------- launch ----------------
extern "C" void kernel_launch(void* const* d_in, const int* in_sizes, int n_in,
                              void* d_out, int out_size)
{
    const float* inputs = (const float*)d_in[0];
    const float* H0     = (const float*)d_in[1];
    const float* C0     = (const float*)d_in[2];
    const float* c2     = (const float*)d_in[3];
    const float* sf     = (const float*)d_in[4];
    const float* w1     = (const float*)d_in[5];
    const float* b1     = (const float*)d_in[6];
    const float* w2     = (const float*)d_in[7];
    const float* b2     = (const float*)d_in[8];
    const float* w3     = (const float*)d_in[9];
    const float* b3     = (const float*)d_in[10];
    const float* w4     = (const float*)d_in[11];
    const float* b4     = (const float*)d_in[12];
    float* out = (float*)d_out;

    __half *actAh, *actBh, *w2p, *w3p;
    float *actC;
    cudaGetSymbolAddress((void**)&actAh, g_actAh);
    cudaGetSymbolAddress((void**)&actBh, g_actBh);
    cudaGetSymbolAddress((void**)&actC,  g_actC);
    cudaGetSymbolAddress((void**)&w2p,   g_w2p);
    cudaGetSymbolAddress((void**)&w3p,   g_w3p);

    const int SM2 = 48960 + 36864;         // 85824
    const int SM3 = 48960 + 18432;         // 67392 -> 2 CTAs/SM
    const int SM4 = (324 * 36 + 288) * 4;  // 47808

    cudaFuncSetAttribute(conv2_mma, cudaFuncAttributeMaxDynamicSharedMemorySize, SM2);
    cudaFuncSetAttribute(conv3_mma, cudaFuncAttributeMaxDynamicSharedMemorySize, SM3);
    cudaFuncSetAttribute(conv4_k,   cudaFuncAttributeMaxDynamicSharedMemorySize, SM4);

    w_pack_k<<<144, 256>>>(w2, w3, w2p, w3p);

    dim3 pg(WID / 16, HGT / 16, BATCH);   // (16, 16, 8)
    fuse_pc1_k<<<pg, 256>>>(inputs, H0, C0, c2, sf, w1, b1, out, actAh);

    dim3 tcg(WID / 32, HGT / 16, BATCH);  // (8, 16, 8)
    conv2_mma<<<tcg, 1024, SM2>>>(actAh, w2p, b2, actBh);
    conv3_mma<<<tcg,  512, SM3>>>(actBh, w3p, b3, actC);

    conv4_k<<<pg, 256, SM4>>>(actC, w4, b4, sf, out);
}